// round 1
// baseline (speedup 1.0000x reference)
#include <cuda_runtime.h>
#include <cstdint>
#include <cstddef>

#define N_NODES 8192
#define K_NBR   8
#define H_DIM   512
#define X_DIM   512

// ---------------- scratch (static device arrays; no runtime allocs) ----------------
__device__ float g_ioux[(size_t)N_NODES * 3 * H_DIM];  // x @ W_iou            [N, 3H]
__device__ float g_wfx [(size_t)N_NODES * H_DIM];      // x @ W_f              [N, H]
__device__ float g_S   [(size_t)N_NODES * 2 * H_DIM];  // [s0 | s1]            [N, 2H]
__device__ float g_cagg[(size_t)N_NODES * H_DIM];      // sum_k f * c_mail     [N, H]

// ---------------- helpers ----------------
__device__ __forceinline__ uint32_t f2tf(float x) {
    uint32_t r;
    asm("cvt.rna.tf32.f32 %0, %1;" : "=r"(r) : "f"(x));
    return r;
}

__device__ __forceinline__ void mma8(float (&c)[4], const uint32_t (&a)[4], const uint32_t (&b)[2]) {
    asm volatile(
        "mma.sync.aligned.m16n8k8.row.col.f32.tf32.tf32.f32 "
        "{%0,%1,%2,%3}, {%4,%5,%6,%7}, {%8,%9}, {%0,%1,%2,%3};"
        : "+f"(c[0]), "+f"(c[1]), "+f"(c[2]), "+f"(c[3])
        : "r"(a[0]), "r"(a[1]), "r"(a[2]), "r"(a[3]), "r"(b[0]), "r"(b[1]));
}

__device__ __forceinline__ float sigmoidf_(float z) {
    return __fdividef(1.0f, 1.0f + __expf(-z));
}

// ---------------- shared tiles ----------------
// CTA tile: 128(M) x 64(N) x 32(K). 256 threads = 8 warps as 4(M) x 2(N), warp tile 32x32.
// Padding chosen for conflict-free mma-fragment LDS: A stride 36 words, B stride 72 words.
template <int NB>
struct Smem {
    uint32_t A[128][36];
    uint32_t B[NB][32][72];
};

// ---------------- generic tf32 GEMM mainloop with register double-buffering ----------
// Computes acc[b] += A_tile @ Bp[b]_tile for NB B-matrices sharing the same A tile.
template <int NB>
__device__ __forceinline__ void gemm_main(
    const float* __restrict__ A, int lda,
    const float* const (&Bp)[NB], int ldb,
    int Kdim, int m0, int n0,
    Smem<NB>& sm, float (&acc)[NB][2][4][4])
{
    const int tid  = threadIdx.x;
    const int lane = tid & 31;
    const int wm   = (tid >> 5) >> 1;   // 0..3
    const int wn   = (tid >> 5) & 1;    // 0..1
    const int g    = lane >> 2;         // 0..7
    const int t    = lane & 3;          // 0..3

    const int ar  = tid >> 3;           // A: row 0..31 (x4 passes)
    const int ac4 = (tid & 7) << 2;     // A: col 0..28
    const int bkr = tid >> 4;           // B: k 0..15 (x2 passes)
    const int bc4 = (tid & 15) << 2;    // B: col 0..60

    float4 rA[4];
    float4 rB[NB][2];

    auto ldA = [&](int kt) {
#pragma unroll
        for (int rr = 0; rr < 4; rr++)
            rA[rr] = *reinterpret_cast<const float4*>(
                A + (size_t)(m0 + ar + rr * 32) * lda + kt + ac4);
    };
    auto ldB = [&](int kt) {
#pragma unroll
        for (int b = 0; b < NB; b++)
#pragma unroll
            for (int p = 0; p < 2; p++)
                rB[b][p] = *reinterpret_cast<const float4*>(
                    Bp[b] + (size_t)(kt + bkr + p * 16) * ldb + n0 + bc4);
    };
    auto stS = [&]() {
#pragma unroll
        for (int rr = 0; rr < 4; rr++) {
            uint4 u;
            u.x = f2tf(rA[rr].x); u.y = f2tf(rA[rr].y);
            u.z = f2tf(rA[rr].z); u.w = f2tf(rA[rr].w);
            *reinterpret_cast<uint4*>(&sm.A[ar + rr * 32][ac4]) = u;
        }
#pragma unroll
        for (int b = 0; b < NB; b++)
#pragma unroll
            for (int p = 0; p < 2; p++) {
                uint4 u;
                u.x = f2tf(rB[b][p].x); u.y = f2tf(rB[b][p].y);
                u.z = f2tf(rB[b][p].z); u.w = f2tf(rB[b][p].w);
                *reinterpret_cast<uint4*>(&sm.B[b][bkr + p * 16][bc4]) = u;
            }
    };

    ldA(0); ldB(0);
    stS();
    __syncthreads();

    for (int kt = 0; kt < Kdim; kt += 32) {
        const bool nxt = (kt + 32) < Kdim;
        if (nxt) { ldA(kt + 32); ldB(kt + 32); }   // LDGs in flight over compute

#pragma unroll
        for (int ks = 0; ks < 4; ks++) {
            const int kb = ks << 3;
            uint32_t af[2][4];
#pragma unroll
            for (int mf = 0; mf < 2; mf++) {
                const int rb = wm * 32 + mf * 16;
                af[mf][0] = sm.A[rb + g    ][kb + t];
                af[mf][1] = sm.A[rb + g + 8][kb + t];
                af[mf][2] = sm.A[rb + g    ][kb + t + 4];
                af[mf][3] = sm.A[rb + g + 8][kb + t + 4];
            }
#pragma unroll
            for (int b = 0; b < NB; b++) {
#pragma unroll
                for (int nf = 0; nf < 4; nf++) {
                    const int cb = wn * 32 + nf * 8 + g;
                    uint32_t bfr[2];
                    bfr[0] = sm.B[b][kb + t    ][cb];
                    bfr[1] = sm.B[b][kb + t + 4][cb];
#pragma unroll
                    for (int mf = 0; mf < 2; mf++)
                        mma8(acc[b][mf][nf], af[mf], bfr);
                }
            }
        }
        __syncthreads();
        if (nxt) { stS(); __syncthreads(); }
    }
}

// ---------------- K0: mailbox reduction -> g_S = [s0 | s1] -----------------------------
__global__ void k_reduce(const float* __restrict__ hm, const float* __restrict__ edge) {
    const int idx = blockIdx.x * blockDim.x + threadIdx.x;   // 0 .. N*H-1
    const int n = idx >> 9;
    const int j = idx & (H_DIM - 1);
    const float* p  = hm + (size_t)n * (K_NBR * H_DIM) + j;
    const float* ep = edge + n * K_NBR;
    float s0 = 0.f, s1 = 0.f;
#pragma unroll
    for (int k = 0; k < K_NBR; k++) {
        const float e = __ldg(ep + k);
        const float v = __ldg(p + k * H_DIM);
        s1 += e * v;
        s0 += v - e * v;   // (1-e)*v, exact for e in {0,1}
    }
    g_S[(size_t)n * (2 * H_DIM) + j]         = s0;
    g_S[(size_t)n * (2 * H_DIM) + H_DIM + j] = s1;
}

// ---------------- K1: x @ W  (which=0 -> g_ioux [N,3H], which=1 -> g_wfx [N,H]) --------
__global__ __launch_bounds__(256, 1) void k_gemm_x(
    const float* __restrict__ A, const float* __restrict__ B, int which)
{
    __shared__ Smem<1> sm;
    const int m0 = blockIdx.y * 128, n0 = blockIdx.x * 64;
    float acc[1][2][4][4];
#pragma unroll
    for (int i = 0; i < 32; i++) (&acc[0][0][0][0])[i] = 0.f;

    const int ld = which ? H_DIM : 3 * H_DIM;
    float* C = which ? g_wfx : g_ioux;

    const float* const Bp[1] = {B};
    gemm_main<1>(A, X_DIM, Bp, ld, X_DIM, m0, n0, sm, acc);

    const int tid = threadIdx.x, lane = tid & 31;
    const int wm = (tid >> 5) >> 1, wn = (tid >> 5) & 1;
    const int g = lane >> 2, t = lane & 3;
#pragma unroll
    for (int mf = 0; mf < 2; mf++)
#pragma unroll
        for (int rh = 0; rh < 2; rh++) {
            const int row = m0 + wm * 32 + mf * 16 + rh * 8 + g;
#pragma unroll
            for (int nf = 0; nf < 4; nf++) {
                const int col = n0 + wn * 32 + nf * 8 + t * 2;
                *reinterpret_cast<float2*>(C + (size_t)row * ld + col) =
                    make_float2(acc[0][mf][nf][rh * 2], acc[0][mf][nf][rh * 2 + 1]);
            }
        }
}

// ---------------- K3: fused f-gate GEMM -> g_cagg --------------------------------------
// acc0 = hm @ U_f[0:H,:], acc1 = hm @ U_f[H:2H,:]; per-row label select, sigmoid,
// * c_mail, in-warp sum over the 8 neighbor rows of each node.
__global__ __launch_bounds__(256, 1) void k_fgemm(
    const float* __restrict__ hm, const float* __restrict__ Uf,
    const float* __restrict__ edge, const float* __restrict__ bf_,
    const float* __restrict__ cmail)
{
    __shared__ Smem<2> sm;
    const int m0 = blockIdx.y * 128, n0 = blockIdx.x * 64;
    float acc[2][2][4][4];
#pragma unroll
    for (int i = 0; i < 64; i++) (&acc[0][0][0][0])[i] = 0.f;

    const float* const Bp[2] = {Uf, Uf + (size_t)H_DIM * H_DIM};
    gemm_main<2>(hm, H_DIM, Bp, H_DIM, H_DIM, m0, n0, sm, acc);

    const int tid = threadIdx.x, lane = tid & 31;
    const int wm = (tid >> 5) >> 1, wn = (tid >> 5) & 1;
    const int g = lane >> 2, t = lane & 3;
#pragma unroll
    for (int mf = 0; mf < 2; mf++)
#pragma unroll
        for (int rh = 0; rh < 2; rh++) {
            const int row  = m0 + wm * 32 + mf * 16 + rh * 8 + g;  // global mailbox row n*8+k
            const int node = row >> 3;
            const float e  = __ldg(edge + row);
#pragma unroll
            for (int nf = 0; nf < 4; nf++) {
                const int col = n0 + wn * 32 + nf * 8 + t * 2;
                float v[2];
#pragma unroll
                for (int q = 0; q < 2; q++) {
                    const float lo  = acc[0][mf][nf][rh * 2 + q];
                    const float hi  = acc[1][mf][nf][rh * 2 + q];
                    const float sel = lo + e * (hi - lo);          // exact for e in {0,1}
                    const float z   = g_wfx[(size_t)node * H_DIM + col + q] + sel
                                      + __ldg(bf_ + col + q);
                    const float f   = sigmoidf_(z);
                    v[q] = f * __ldg(cmail + (size_t)row * H_DIM + col + q);
                }
                // rows {node*8 .. node*8+7} live on lanes differing only in g-bits -> shfl sum
#pragma unroll
                for (int msk = 4; msk < 32; msk <<= 1) {
                    v[0] += __shfl_xor_sync(0xffffffffu, v[0], msk);
                    v[1] += __shfl_xor_sync(0xffffffffu, v[1], msk);
                }
                if (g == 0)
                    *reinterpret_cast<float2*>(&g_cagg[(size_t)node * H_DIM + col]) =
                        make_float2(v[0], v[1]);
            }
        }
}

// ---------------- K2: [s0|s1] @ U_iou (i/o/u triple-accumulator) + final cell ----------
__global__ __launch_bounds__(256, 1) void k_final(
    const float* __restrict__ Uiou, const float* __restrict__ biou,
    float* __restrict__ out)
{
    __shared__ Smem<3> sm;
    const int m0 = blockIdx.y * 128, n0 = blockIdx.x * 64;
    float acc[3][2][4][4];
#pragma unroll
    for (int i = 0; i < 96; i++) (&acc[0][0][0][0])[i] = 0.f;

    const float* const Bp[3] = {Uiou, Uiou + H_DIM, Uiou + 2 * H_DIM};
    gemm_main<3>(g_S, 2 * H_DIM, Bp, 3 * H_DIM, 2 * H_DIM, m0, n0, sm, acc);

    const int tid = threadIdx.x, lane = tid & 31;
    const int wm = (tid >> 5) >> 1, wn = (tid >> 5) & 1;
    const int g = lane >> 2, t = lane & 3;
#pragma unroll
    for (int mf = 0; mf < 2; mf++)
#pragma unroll
        for (int rh = 0; rh < 2; rh++) {
            const int row = m0 + wm * 32 + mf * 16 + rh * 8 + g;
#pragma unroll
            for (int nf = 0; nf < 4; nf++) {
                const int colb = n0 + wn * 32 + nf * 8 + t * 2;
                float hv[2], cv[2];
#pragma unroll
                for (int q = 0; q < 2; q++) {
                    const int col = colb + q;
                    const float* ip = g_ioux + (size_t)row * (3 * H_DIM) + col;
                    const float ai = acc[0][mf][nf][rh * 2 + q] + ip[0]
                                     + __ldg(biou + col);
                    const float ao = acc[1][mf][nf][rh * 2 + q] + ip[H_DIM]
                                     + __ldg(biou + col + H_DIM);
                    const float au = acc[2][mf][nf][rh * 2 + q] + ip[2 * H_DIM]
                                     + __ldg(biou + col + 2 * H_DIM);
                    const float iv = sigmoidf_(ai);
                    const float ov = sigmoidf_(ao);
                    const float uv = tanhf(au);
                    const float c  = iv * uv + g_cagg[(size_t)row * H_DIM + col];
                    cv[q] = c;
                    hv[q] = ov * tanhf(c);
                }
                *reinterpret_cast<float2*>(out + (size_t)row * H_DIM + colb) =
                    make_float2(hv[0], hv[1]);
                *reinterpret_cast<float2*>(out + (size_t)N_NODES * H_DIM
                                               + (size_t)row * H_DIM + colb) =
                    make_float2(cv[0], cv[1]);
            }
        }
}

// ---------------- launch ----------------
extern "C" void kernel_launch(void* const* d_in, const int* in_sizes, int n_in,
                              void* d_out, int out_size)
{
    const float* x    = (const float*)d_in[0];
    const float* hm   = (const float*)d_in[1];
    const float* cm   = (const float*)d_in[2];
    const float* edge = (const float*)d_in[3];
    const float* Wiou = (const float*)d_in[4];
    const float* Wf   = (const float*)d_in[5];
    const float* Uiou = (const float*)d_in[6];
    const float* Uf   = (const float*)d_in[7];
    const float* biou = (const float*)d_in[8];
    const float* bf   = (const float*)d_in[9];
    float* out = (float*)d_out;

    // K0: mailbox label-routed reduction -> g_S
    k_reduce<<<(N_NODES * H_DIM) / 256, 256>>>(hm, edge);
    // K1: node transforms -> g_ioux, g_wfx
    k_gemm_x<<<dim3((3 * H_DIM) / 64, N_NODES / 128), 256>>>(x, Wiou, 0);
    k_gemm_x<<<dim3(H_DIM / 64,       N_NODES / 128), 256>>>(x, Wf,   1);
    // K3: fused forget-gate GEMM + sigmoid + c_mail product + per-node sum -> g_cagg
    k_fgemm<<<dim3(H_DIM / 64, (N_NODES * K_NBR) / 128), 256>>>(hm, Uf, edge, bf, cm);
    // K2: iou GEMM (i/o/u fused) + cell update -> out = [h | c]
    k_final<<<dim3(H_DIM / 64, N_NODES / 128), 256>>>(Uiou, biou, out);
}

// round 2
// speedup vs baseline: 1.0016x; 1.0016x over previous
#include <cuda_runtime.h>
#include <cstdint>
#include <cstddef>

#define N_NODES 8192
#define K_NBR   8
#define H_DIM   512
#define X_DIM   512

// ---------------- scratch (static device arrays; no runtime allocs) ----------------
__device__ float g_ioux[(size_t)N_NODES * 3 * H_DIM];  // x @ W_iou            [N, 3H]
__device__ float g_wfx [(size_t)N_NODES * H_DIM];      // x @ W_f              [N, H]
__device__ float g_S   [(size_t)N_NODES * 2 * H_DIM];  // [s0 | s1]            [N, 2H]
__device__ float g_cagg[(size_t)N_NODES * H_DIM];      // sum_k f * c_mail     [N, H]

// ---------------- helpers ----------------
__device__ __forceinline__ uint32_t f2tf(float x) {
    uint32_t r;
    asm("cvt.rna.tf32.f32 %0, %1;" : "=r"(r) : "f"(x));
    return r;
}

__device__ __forceinline__ void mma8(float (&c)[4], const uint32_t (&a)[4], const uint32_t (&b)[2]) {
    asm volatile(
        "mma.sync.aligned.m16n8k8.row.col.f32.tf32.tf32.f32 "
        "{%0,%1,%2,%3}, {%4,%5,%6,%7}, {%8,%9}, {%0,%1,%2,%3};"
        : "+f"(c[0]), "+f"(c[1]), "+f"(c[2]), "+f"(c[3])
        : "r"(a[0]), "r"(a[1]), "r"(a[2]), "r"(a[3]), "r"(b[0]), "r"(b[1]));
}

__device__ __forceinline__ float sigmoidf_(float z) {
    return __fdividef(1.0f, 1.0f + __expf(-z));
}

// ---------------- shared tiles ----------------
// CTA tile: 128(M) x 64(N) x 32(K). 256 threads = 8 warps as 4(M) x 2(N), warp tile 32x32.
// Padding chosen for conflict-free mma-fragment LDS: A stride 36 words, B stride 72 words.
template <int NB>
struct Smem {
    uint32_t A[128][36];
    uint32_t B[NB][32][72];
};

// ---------------- generic tf32 GEMM mainloop with register double-buffering ----------
// Computes acc[b] += A_tile @ Bp[b]_tile for NB B-matrices sharing the same A tile.
template <int NB>
__device__ __forceinline__ void gemm_main(
    const float* __restrict__ A, int lda,
    const float* const (&Bp)[NB], int ldb,
    int Kdim, int m0, int n0,
    Smem<NB>& sm, float (&acc)[NB][2][4][4])
{
    const int tid  = threadIdx.x;
    const int lane = tid & 31;
    const int wm   = (tid >> 5) >> 1;   // 0..3
    const int wn   = (tid >> 5) & 1;    // 0..1
    const int g    = lane >> 2;         // 0..7
    const int t    = lane & 3;          // 0..3

    const int ar  = tid >> 3;           // A: row 0..31 (x4 passes)
    const int ac4 = (tid & 7) << 2;     // A: col 0..28
    const int bkr = tid >> 4;           // B: k 0..15 (x2 passes)
    const int bc4 = (tid & 15) << 2;    // B: col 0..60

    float4 rA[4];
    float4 rB[NB][2];

    auto ldA = [&](int kt) {
#pragma unroll
        for (int rr = 0; rr < 4; rr++)
            rA[rr] = *reinterpret_cast<const float4*>(
                A + (size_t)(m0 + ar + rr * 32) * lda + kt + ac4);
    };
    auto ldB = [&](int kt) {
#pragma unroll
        for (int b = 0; b < NB; b++)
#pragma unroll
            for (int p = 0; p < 2; p++)
                rB[b][p] = *reinterpret_cast<const float4*>(
                    Bp[b] + (size_t)(kt + bkr + p * 16) * ldb + n0 + bc4);
    };
    auto stS = [&]() {
#pragma unroll
        for (int rr = 0; rr < 4; rr++) {
            uint4 u;
            u.x = f2tf(rA[rr].x); u.y = f2tf(rA[rr].y);
            u.z = f2tf(rA[rr].z); u.w = f2tf(rA[rr].w);
            *reinterpret_cast<uint4*>(&sm.A[ar + rr * 32][ac4]) = u;
        }
#pragma unroll
        for (int b = 0; b < NB; b++)
#pragma unroll
            for (int p = 0; p < 2; p++) {
                uint4 u;
                u.x = f2tf(rB[b][p].x); u.y = f2tf(rB[b][p].y);
                u.z = f2tf(rB[b][p].z); u.w = f2tf(rB[b][p].w);
                *reinterpret_cast<uint4*>(&sm.B[b][bkr + p * 16][bc4]) = u;
            }
    };

    ldA(0); ldB(0);
    stS();
    __syncthreads();

    for (int kt = 0; kt < Kdim; kt += 32) {
        const bool nxt = (kt + 32) < Kdim;
        if (nxt) { ldA(kt + 32); ldB(kt + 32); }   // LDGs in flight over compute

#pragma unroll
        for (int ks = 0; ks < 4; ks++) {
            const int kb = ks << 3;
            uint32_t af[2][4];
#pragma unroll
            for (int mf = 0; mf < 2; mf++) {
                const int rb = wm * 32 + mf * 16;
                af[mf][0] = sm.A[rb + g    ][kb + t];
                af[mf][1] = sm.A[rb + g + 8][kb + t];
                af[mf][2] = sm.A[rb + g    ][kb + t + 4];
                af[mf][3] = sm.A[rb + g + 8][kb + t + 4];
            }
#pragma unroll
            for (int b = 0; b < NB; b++) {
#pragma unroll
                for (int nf = 0; nf < 4; nf++) {
                    const int cb = wn * 32 + nf * 8 + g;
                    uint32_t bfr[2];
                    bfr[0] = sm.B[b][kb + t    ][cb];
                    bfr[1] = sm.B[b][kb + t + 4][cb];
#pragma unroll
                    for (int mf = 0; mf < 2; mf++)
                        mma8(acc[b][mf][nf], af[mf], bfr);
                }
            }
        }
        __syncthreads();
        if (nxt) { stS(); __syncthreads(); }
    }
}

// ---------------- K0: mailbox reduction -> g_S = [s0 | s1] -----------------------------
__global__ void k_reduce(const float* __restrict__ hm, const float* __restrict__ edge) {
    const int idx = blockIdx.x * blockDim.x + threadIdx.x;   // 0 .. N*H-1
    const int n = idx >> 9;
    const int j = idx & (H_DIM - 1);
    const float* p  = hm + (size_t)n * (K_NBR * H_DIM) + j;
    const float* ep = edge + n * K_NBR;
    float s0 = 0.f, s1 = 0.f;
#pragma unroll
    for (int k = 0; k < K_NBR; k++) {
        const float e = __ldg(ep + k);
        const float v = __ldg(p + k * H_DIM);
        s1 += e * v;
        s0 += v - e * v;   // (1-e)*v, exact for e in {0,1}
    }
    g_S[(size_t)n * (2 * H_DIM) + j]         = s0;
    g_S[(size_t)n * (2 * H_DIM) + H_DIM + j] = s1;
}

// ---------------- K1: x @ W  (which=0 -> g_ioux [N,3H], which=1 -> g_wfx [N,H]) --------
__global__ __launch_bounds__(256, 1) void k_gemm_x(
    const float* __restrict__ A, const float* __restrict__ B, int which)
{
    __shared__ Smem<1> sm;
    const int m0 = blockIdx.y * 128, n0 = blockIdx.x * 64;
    float acc[1][2][4][4];
#pragma unroll
    for (int i = 0; i < 32; i++) (&acc[0][0][0][0])[i] = 0.f;

    const int ld = which ? H_DIM : 3 * H_DIM;
    float* C = which ? g_wfx : g_ioux;

    const float* const Bp[1] = {B};
    gemm_main<1>(A, X_DIM, Bp, ld, X_DIM, m0, n0, sm, acc);

    const int tid = threadIdx.x, lane = tid & 31;
    const int wm = (tid >> 5) >> 1, wn = (tid >> 5) & 1;
    const int g = lane >> 2, t = lane & 3;
#pragma unroll
    for (int mf = 0; mf < 2; mf++)
#pragma unroll
        for (int rh = 0; rh < 2; rh++) {
            const int row = m0 + wm * 32 + mf * 16 + rh * 8 + g;
#pragma unroll
            for (int nf = 0; nf < 4; nf++) {
                const int col = n0 + wn * 32 + nf * 8 + t * 2;
                *reinterpret_cast<float2*>(C + (size_t)row * ld + col) =
                    make_float2(acc[0][mf][nf][rh * 2], acc[0][mf][nf][rh * 2 + 1]);
            }
        }
}

// ---------------- K3: fused f-gate GEMM -> g_cagg --------------------------------------
// acc0 = hm @ U_f[0:H,:], acc1 = hm @ U_f[H:2H,:]; per-row label select, sigmoid,
// * c_mail, in-warp sum over the 8 neighbor rows of each node.
__global__ __launch_bounds__(256, 1) void k_fgemm(
    const float* __restrict__ hm, const float* __restrict__ Uf,
    const float* __restrict__ edge, const float* __restrict__ bf_,
    const float* __restrict__ cmail)
{
    __shared__ Smem<2> sm;
    const int m0 = blockIdx.y * 128, n0 = blockIdx.x * 64;
    float acc[2][2][4][4];
#pragma unroll
    for (int i = 0; i < 64; i++) (&acc[0][0][0][0])[i] = 0.f;

    const float* const Bp[2] = {Uf, Uf + (size_t)H_DIM * H_DIM};
    gemm_main<2>(hm, H_DIM, Bp, H_DIM, H_DIM, m0, n0, sm, acc);

    const int tid = threadIdx.x, lane = tid & 31;
    const int wm = (tid >> 5) >> 1, wn = (tid >> 5) & 1;
    const int g = lane >> 2, t = lane & 3;
#pragma unroll
    for (int mf = 0; mf < 2; mf++)
#pragma unroll
        for (int rh = 0; rh < 2; rh++) {
            const int row  = m0 + wm * 32 + mf * 16 + rh * 8 + g;  // global mailbox row n*8+k
            const int node = row >> 3;
            const float e  = __ldg(edge + row);
#pragma unroll
            for (int nf = 0; nf < 4; nf++) {
                const int col = n0 + wn * 32 + nf * 8 + t * 2;
                float v[2];
#pragma unroll
                for (int q = 0; q < 2; q++) {
                    const float lo  = acc[0][mf][nf][rh * 2 + q];
                    const float hi  = acc[1][mf][nf][rh * 2 + q];
                    const float sel = lo + e * (hi - lo);          // exact for e in {0,1}
                    const float z   = g_wfx[(size_t)node * H_DIM + col + q] + sel
                                      + __ldg(bf_ + col + q);
                    const float f   = sigmoidf_(z);
                    v[q] = f * __ldg(cmail + (size_t)row * H_DIM + col + q);
                }
                // rows {node*8 .. node*8+7} live on lanes differing only in g-bits -> shfl sum
#pragma unroll
                for (int msk = 4; msk < 32; msk <<= 1) {
                    v[0] += __shfl_xor_sync(0xffffffffu, v[0], msk);
                    v[1] += __shfl_xor_sync(0xffffffffu, v[1], msk);
                }
                if (g == 0)
                    *reinterpret_cast<float2*>(&g_cagg[(size_t)node * H_DIM + col]) =
                        make_float2(v[0], v[1]);
            }
        }
}

// ---------------- K2: [s0|s1] @ U_iou (i/o/u triple-accumulator) + final cell ----------
__global__ __launch_bounds__(256, 1) void k_final(
    const float* __restrict__ Uiou, const float* __restrict__ biou,
    float* __restrict__ out)
{
    __shared__ Smem<3> sm;
    const int m0 = blockIdx.y * 128, n0 = blockIdx.x * 64;
    float acc[3][2][4][4];
#pragma unroll
    for (int i = 0; i < 96; i++) (&acc[0][0][0][0])[i] = 0.f;

    const float* const Bp[3] = {Uiou, Uiou + H_DIM, Uiou + 2 * H_DIM};
    gemm_main<3>(g_S, 2 * H_DIM, Bp, 3 * H_DIM, 2 * H_DIM, m0, n0, sm, acc);

    const int tid = threadIdx.x, lane = tid & 31;
    const int wm = (tid >> 5) >> 1, wn = (tid >> 5) & 1;
    const int g = lane >> 2, t = lane & 3;
#pragma unroll
    for (int mf = 0; mf < 2; mf++)
#pragma unroll
        for (int rh = 0; rh < 2; rh++) {
            const int row = m0 + wm * 32 + mf * 16 + rh * 8 + g;
#pragma unroll
            for (int nf = 0; nf < 4; nf++) {
                const int colb = n0 + wn * 32 + nf * 8 + t * 2;
                float hv[2], cv[2];
#pragma unroll
                for (int q = 0; q < 2; q++) {
                    const int col = colb + q;
                    const float* ip = g_ioux + (size_t)row * (3 * H_DIM) + col;
                    const float ai = acc[0][mf][nf][rh * 2 + q] + ip[0]
                                     + __ldg(biou + col);
                    const float ao = acc[1][mf][nf][rh * 2 + q] + ip[H_DIM]
                                     + __ldg(biou + col + H_DIM);
                    const float au = acc[2][mf][nf][rh * 2 + q] + ip[2 * H_DIM]
                                     + __ldg(biou + col + 2 * H_DIM);
                    const float iv = sigmoidf_(ai);
                    const float ov = sigmoidf_(ao);
                    const float uv = tanhf(au);
                    const float c  = iv * uv + g_cagg[(size_t)row * H_DIM + col];
                    cv[q] = c;
                    hv[q] = ov * tanhf(c);
                }
                *reinterpret_cast<float2*>(out + (size_t)row * H_DIM + colb) =
                    make_float2(hv[0], hv[1]);
                *reinterpret_cast<float2*>(out + (size_t)N_NODES * H_DIM
                                               + (size_t)row * H_DIM + colb) =
                    make_float2(cv[0], cv[1]);
            }
        }
}

// ---------------- launch ----------------
extern "C" void kernel_launch(void* const* d_in, const int* in_sizes, int n_in,
                              void* d_out, int out_size)
{
    const float* x    = (const float*)d_in[0];
    const float* hm   = (const float*)d_in[1];
    const float* cm   = (const float*)d_in[2];
    const float* edge = (const float*)d_in[3];
    const float* Wiou = (const float*)d_in[4];
    const float* Wf   = (const float*)d_in[5];
    const float* Uiou = (const float*)d_in[6];
    const float* Uf   = (const float*)d_in[7];
    const float* biou = (const float*)d_in[8];
    const float* bf   = (const float*)d_in[9];
    float* out = (float*)d_out;

    // K0: mailbox label-routed reduction -> g_S
    k_reduce<<<(N_NODES * H_DIM) / 256, 256>>>(hm, edge);
    // K1: node transforms -> g_ioux, g_wfx
    k_gemm_x<<<dim3((3 * H_DIM) / 64, N_NODES / 128), 256>>>(x, Wiou, 0);
    k_gemm_x<<<dim3(H_DIM / 64,       N_NODES / 128), 256>>>(x, Wf,   1);
    // K3: fused forget-gate GEMM + sigmoid + c_mail product + per-node sum -> g_cagg
    k_fgemm<<<dim3(H_DIM / 64, (N_NODES * K_NBR) / 128), 256>>>(hm, Uf, edge, bf, cm);
    // K2: iou GEMM (i/o/u fused) + cell update -> out = [h | c]
    k_final<<<dim3(H_DIM / 64, N_NODES / 128), 256>>>(Uiou, biou, out);
}

// round 5
// speedup vs baseline: 1.4162x; 1.4140x over previous
#include <cuda_runtime.h>
#include <cstdint>
#include <cstddef>

#define N_NODES 8192
#define H_DIM   512
#define M_ROWS  (N_NODES * 8)        // 65536 mailbox rows
#define M_PAD   (M_ROWS + 256)       // 65792 = 514 * 128 (gap >= 128 -> no mixed tiles)
#define SENT    0xFFFFFFFFu

// ---------------- scratch (static device arrays; no runtime allocs) ----------------
__device__ float    g_ioux[(size_t)N_NODES * 1536];  // x @ W_iou                [N, 3H]
__device__ float    g_wfx [(size_t)N_NODES * 512];   // x @ W_f                  [N, H]
__device__ float    g_S   [(size_t)N_NODES * 1024];  // [s0 | s1]                [N, 2H]
__device__ float    g_mid [(size_t)N_NODES * 1536];  // S @ U_iou                [N, 3H]
__device__ float    g_fc  [(size_t)M_ROWS * 512];    // f * c_mail (scattered)   [N*K, H]
__device__ unsigned g_perm[M_PAD];
__device__ unsigned g_ctr[2];

// ---------------- helpers ----------------
__device__ __forceinline__ uint32_t f2tf(float x) {
    uint32_t r;
    asm("cvt.rna.tf32.f32 %0, %1;" : "=r"(r) : "f"(x));
    return r;
}

__device__ __forceinline__ void mma8(float (&c)[4], const uint32_t (&a)[4], const uint32_t (&b)[2]) {
    asm volatile(
        "mma.sync.aligned.m16n8k8.row.col.f32.tf32.tf32.f32 "
        "{%0,%1,%2,%3}, {%4,%5,%6,%7}, {%8,%9}, {%0,%1,%2,%3};"
        : "+f"(c[0]), "+f"(c[1]), "+f"(c[2]), "+f"(c[3])
        : "r"(a[0]), "r"(a[1]), "r"(a[2]), "r"(a[3]), "r"(b[0]), "r"(b[1]));
}

__device__ __forceinline__ float sigmoidf_(float z) {
    return __fdividef(1.0f, 1.0f + __expf(-z));
}

// ---------------- shared tiles (double-buffered, XOR-swizzled, zero padding) ----------
// A tile 128x32, phys col = col ^ ((row&7)<<2). B tile 32x64, phys col = col ^ ((row&3)<<3).
// Exactly 49152 bytes -> 2 CTAs/SM.
struct SmemT {
    uint32_t A[2][128][32];
    uint32_t B[2][32][64];
};

// ---------------- NB=1 tf32 GEMM core: 128x64xK, 256 thr, 2-stage smem pipeline -------
__device__ __forceinline__ void gemm_core(
    const float* a0, const float* a1, const float* a2, const float* a3,  // row base ptrs
    const float* __restrict__ B, int ldb, int Kdim,
    SmemT& sm, float (&acc)[2][4][4])
{
    const int tid  = threadIdx.x;
    const int lane = tid & 31;
    const int wm   = (tid >> 5) >> 1;   // 0..3
    const int wn   = (tid >> 5) & 1;    // 0..1
    const int g    = lane >> 2;         // 0..7
    const int t    = lane & 3;          // 0..3

    const int ar   = tid >> 3;          // A row 0..31 (+32*rr)
    const int ac4  = (tid & 7) << 2;    // A col 0..28
    const int bkr  = tid >> 4;          // B k 0..15 (+16*p)
    const int bc4  = (tid & 15) << 2;   // B col 0..60
    const int aswz = ac4 ^ ((ar & 7) << 2);
    const int bswz = bc4 ^ ((bkr & 3) << 3);

    const float* arow[4] = {a0, a1, a2, a3};
    float4 rA[4];
    float4 rB[2];

    auto ldg = [&](int kt) {
#pragma unroll
        for (int rr = 0; rr < 4; rr++)
            rA[rr] = *reinterpret_cast<const float4*>(arow[rr] + kt + ac4);
#pragma unroll
        for (int p = 0; p < 2; p++)
            rB[p] = *reinterpret_cast<const float4*>(B + (size_t)(kt + bkr + p * 16) * ldb + bc4);
    };
    auto sts = [&](int buf) {
#pragma unroll
        for (int rr = 0; rr < 4; rr++) {
            uint4 u;
            u.x = f2tf(rA[rr].x); u.y = f2tf(rA[rr].y);
            u.z = f2tf(rA[rr].z); u.w = f2tf(rA[rr].w);
            *reinterpret_cast<uint4*>(&sm.A[buf][ar + rr * 32][aswz]) = u;
        }
#pragma unroll
        for (int p = 0; p < 2; p++) {
            uint4 u;
            u.x = f2tf(rB[p].x); u.y = f2tf(rB[p].y);
            u.z = f2tf(rB[p].z); u.w = f2tf(rB[p].w);
            *reinterpret_cast<uint4*>(&sm.B[buf][bkr + p * 16][bswz]) = u;
        }
    };

    ldg(0);
    sts(0);
    __syncthreads();

    int buf = 0;
    for (int kt = 0; kt < Kdim; kt += 32, buf ^= 1) {
        const bool nxt = (kt + 32) < Kdim;
        if (nxt) ldg(kt + 32);          // LDGs in flight over compute

#pragma unroll
        for (int ks = 0; ks < 4; ks++) {
            const int kb = ks << 3;
            const int ca = (kb + t) ^ (g << 2);
            const int cb2 = (kb + t + 4) ^ (g << 2);
            uint32_t af[2][4];
#pragma unroll
            for (int mf = 0; mf < 2; mf++) {
                const int rb = wm * 32 + mf * 16;
                af[mf][0] = sm.A[buf][rb + g    ][ca];
                af[mf][1] = sm.A[buf][rb + 8 + g][ca];
                af[mf][2] = sm.A[buf][rb + g    ][cb2];
                af[mf][3] = sm.A[buf][rb + 8 + g][cb2];
            }
#pragma unroll
            for (int nf = 0; nf < 4; nf++) {
                const int cc = (wn * 32 + nf * 8 + g) ^ (t << 3);
                uint32_t bfr[2];
                bfr[0] = sm.B[buf][kb + t    ][cc];
                bfr[1] = sm.B[buf][kb + t + 4][cc];
#pragma unroll
                for (int mf = 0; mf < 2; mf++)
                    mma8(acc[mf][nf], af[mf], bfr);
            }
        }
        if (nxt) sts(buf ^ 1);          // buf^1 fully consumed before prior sync
        __syncthreads();
    }
}

// ---------------- K_init / K_perm: label-partition of mailbox rows ---------------------
__global__ void k_init() {
    const int idx = blockIdx.x * blockDim.x + threadIdx.x;
    if (idx < M_PAD) g_perm[idx] = SENT;
    if (idx < 2) g_ctr[idx] = 0u;
}

__global__ void k_perm(const float* __restrict__ edge) {
    const int r = blockIdx.x * blockDim.x + threadIdx.x;
    if (r >= M_ROWS) return;
    const float e = edge[r];
    if (e < 0.5f) {
        const unsigned pos = atomicAdd(&g_ctr[0], 1u);
        g_perm[pos] = (unsigned)r;
    } else {
        const unsigned pos = atomicAdd(&g_ctr[1], 1u);
        g_perm[M_PAD - 1 - pos] = (unsigned)r;
    }
}

// ---------------- K_reduce: mailbox label-routed sum -> g_S = [s0 | s1] ----------------
__global__ void k_reduce(const float* __restrict__ hm, const float* __restrict__ edge) {
    const int idx = blockIdx.x * blockDim.x + threadIdx.x;   // 0 .. N*128-1
    const int n = idx >> 7;
    const int j = (idx & 127) << 2;
    const float* p = hm + (size_t)n * 4096 + j;
    float4 s0 = make_float4(0.f, 0.f, 0.f, 0.f);
    float4 s1 = make_float4(0.f, 0.f, 0.f, 0.f);
#pragma unroll
    for (int k = 0; k < 8; k++) {
        const float e = __ldg(edge + n * 8 + k);
        const float4 v = *reinterpret_cast<const float4*>(p + k * 512);
        s1.x += e * v.x; s1.y += e * v.y; s1.z += e * v.z; s1.w += e * v.w;
        s0.x += v.x - e * v.x; s0.y += v.y - e * v.y;
        s0.z += v.z - e * v.z; s0.w += v.w - e * v.w;
    }
    *reinterpret_cast<float4*>(&g_S[(size_t)n * 1024 + j])       = s0;
    *reinterpret_cast<float4*>(&g_S[(size_t)n * 1024 + 512 + j]) = s1;
}

// ---------------- K_A: x @ [W_iou | W_f] -> g_ioux / g_wfx -----------------------------
__global__ __launch_bounds__(256, 2) void k_gemm_x(
    const float* __restrict__ x, const float* __restrict__ Wiou, const float* __restrict__ Wf)
{
    __shared__ SmemT sm;
    const int m0 = blockIdx.y * 128, n0 = blockIdx.x * 64;

    const float* B; int ldb; float* C; int ldc; int ccol;
    if (n0 < 1536) { B = Wiou + n0;          ldb = 1536; C = g_ioux; ldc = 1536; ccol = n0; }
    else           { B = Wf + (n0 - 1536);   ldb = 512;  C = g_wfx;  ldc = 512;  ccol = n0 - 1536; }

    const int tid = threadIdx.x, ar = tid >> 3;
    const float* a0 = x + (size_t)(m0 + ar)      * 512;
    const float* a1 = x + (size_t)(m0 + ar + 32) * 512;
    const float* a2 = x + (size_t)(m0 + ar + 64) * 512;
    const float* a3 = x + (size_t)(m0 + ar + 96) * 512;

    float acc[2][4][4];
    float* af = &acc[0][0][0];
#pragma unroll
    for (int i = 0; i < 32; i++) af[i] = 0.f;

    gemm_core(a0, a1, a2, a3, B, ldb, 512, sm, acc);

    const int lane = tid & 31;
    const int wm = (tid >> 5) >> 1, wn = (tid >> 5) & 1;
    const int g = lane >> 2, t = lane & 3;
#pragma unroll
    for (int mf = 0; mf < 2; mf++)
#pragma unroll
        for (int rh = 0; rh < 2; rh++) {
            const int row = m0 + wm * 32 + mf * 16 + rh * 8 + g;
#pragma unroll
            for (int nf = 0; nf < 4; nf++) {
                const int col = ccol + wn * 32 + nf * 8 + t * 2;
                *reinterpret_cast<float2*>(C + (size_t)row * ldc + col) =
                    make_float2(acc[mf][nf][rh * 2], acc[mf][nf][rh * 2 + 1]);
            }
        }
}

// ---------------- K_F: gathered f-gate GEMM (NB=1, label-uniform tiles) ----------------
__global__ __launch_bounds__(256, 2) void k_fgemm(
    const float* __restrict__ hm, const float* __restrict__ Uf,
    const float* __restrict__ bf_, const float* __restrict__ cmail)
{
    __shared__ SmemT sm;
    const int m0 = blockIdx.y * 128, n0 = blockIdx.x * 64;

    const unsigned c0 = g_ctr[0];                       // finalized by k_perm
    const int label = (m0 < (int)c0) ? 0 : 1;           // tiles never mix labels
    const float* B = Uf + (size_t)label * 512 * 512 + n0;

    const int tid = threadIdx.x, ar = tid >> 3;
    const float* ap[4];
#pragma unroll
    for (int rr = 0; rr < 4; rr++) {
        const unsigned p = g_perm[m0 + ar + rr * 32];
        ap[rr] = hm + (size_t)(p == SENT ? 0u : p) * 512;
    }

    float acc[2][4][4];
    float* af = &acc[0][0][0];
#pragma unroll
    for (int i = 0; i < 32; i++) af[i] = 0.f;

    gemm_core(ap[0], ap[1], ap[2], ap[3], B, 512, 512, sm, acc);

    const int lane = tid & 31;
    const int wm = (tid >> 5) >> 1, wn = (tid >> 5) & 1;
    const int g = lane >> 2, t = lane & 3;
#pragma unroll
    for (int mf = 0; mf < 2; mf++)
#pragma unroll
        for (int rh = 0; rh < 2; rh++) {
            const unsigned p = g_perm[m0 + wm * 32 + mf * 16 + rh * 8 + g];
            if (p == SENT) continue;
            const int node = (int)(p >> 3);
#pragma unroll
            for (int nf = 0; nf < 4; nf++) {
                const int col = n0 + wn * 32 + nf * 8 + t * 2;
                float v[2];
#pragma unroll
                for (int q = 0; q < 2; q++) {
                    const float z = g_wfx[(size_t)node * 512 + col + q]
                                  + acc[mf][nf][rh * 2 + q]
                                  + __ldg(bf_ + col + q);
                    v[q] = sigmoidf_(z) * __ldg(cmail + (size_t)p * 512 + col + q);
                }
                *reinterpret_cast<float2*>(&g_fc[(size_t)p * 512 + col]) =
                    make_float2(v[0], v[1]);
            }
        }
}

// ---------------- K_G: S @ U_iou -> g_mid ----------------------------------------------
__global__ __launch_bounds__(256, 2) void k_gemm_iou(const float* __restrict__ Uiou)
{
    __shared__ SmemT sm;
    const int m0 = blockIdx.y * 128, n0 = blockIdx.x * 64;
    const float* B = Uiou + n0;

    const int tid = threadIdx.x, ar = tid >> 3;
    const float* a0 = g_S + (size_t)(m0 + ar)      * 1024;
    const float* a1 = g_S + (size_t)(m0 + ar + 32) * 1024;
    const float* a2 = g_S + (size_t)(m0 + ar + 64) * 1024;
    const float* a3 = g_S + (size_t)(m0 + ar + 96) * 1024;

    float acc[2][4][4];
    float* af = &acc[0][0][0];
#pragma unroll
    for (int i = 0; i < 32; i++) af[i] = 0.f;

    gemm_core(a0, a1, a2, a3, B, 1536, 1024, sm, acc);

    const int lane = tid & 31;
    const int wm = (tid >> 5) >> 1, wn = (tid >> 5) & 1;
    const int g = lane >> 2, t = lane & 3;
#pragma unroll
    for (int mf = 0; mf < 2; mf++)
#pragma unroll
        for (int rh = 0; rh < 2; rh++) {
            const int row = m0 + wm * 32 + mf * 16 + rh * 8 + g;
#pragma unroll
            for (int nf = 0; nf < 4; nf++) {
                const int col = n0 + wn * 32 + nf * 8 + t * 2;
                *reinterpret_cast<float2*>(&g_mid[(size_t)row * 1536 + col]) =
                    make_float2(acc[mf][nf][rh * 2], acc[mf][nf][rh * 2 + 1]);
            }
        }
}

// ---------------- K_E: elementwise finalize (iou + c_agg sum) -> out = [h | c] ---------
__global__ void k_final(const float* __restrict__ biou, float* __restrict__ out)
{
    const int idx = blockIdx.x * blockDim.x + threadIdx.x;   // 0 .. N*256-1
    const int n = idx >> 8;
    const int col = (idx & 255) << 1;
    const size_t b3 = (size_t)n * 1536 + col;

    const float2 mi = *reinterpret_cast<const float2*>(&g_mid[b3]);
    const float2 mo = *reinterpret_cast<const float2*>(&g_mid[b3 + 512]);
    const float2 mu = *reinterpret_cast<const float2*>(&g_mid[b3 + 1024]);
    const float2 xi = *reinterpret_cast<const float2*>(&g_ioux[b3]);
    const float2 xo = *reinterpret_cast<const float2*>(&g_ioux[b3 + 512]);
    const float2 xu = *reinterpret_cast<const float2*>(&g_ioux[b3 + 1024]);
    const float2 bi = *reinterpret_cast<const float2*>(&biou[col]);
    const float2 bo = *reinterpret_cast<const float2*>(&biou[col + 512]);
    const float2 bu = *reinterpret_cast<const float2*>(&biou[col + 1024]);

    float cax = 0.f, cay = 0.f;
#pragma unroll
    for (int k = 0; k < 8; k++) {
        const float2 v = *reinterpret_cast<const float2*>(&g_fc[((size_t)n * 8 + k) * 512 + col]);
        cax += v.x; cay += v.y;
    }

    const float iv0 = sigmoidf_(mi.x + xi.x + bi.x);
    const float iv1 = sigmoidf_(mi.y + xi.y + bi.y);
    const float ov0 = sigmoidf_(mo.x + xo.x + bo.x);
    const float ov1 = sigmoidf_(mo.y + xo.y + bo.y);
    const float uv0 = tanhf(mu.x + xu.x + bu.x);
    const float uv1 = tanhf(mu.y + xu.y + bu.y);

    const float c0 = iv0 * uv0 + cax;
    const float c1 = iv1 * uv1 + cay;
    const float h0 = ov0 * tanhf(c0);
    const float h1 = ov1 * tanhf(c1);

    *reinterpret_cast<float2*>(&out[(size_t)n * 512 + col]) = make_float2(h0, h1);
    *reinterpret_cast<float2*>(&out[(size_t)(N_NODES + n) * 512 + col]) = make_float2(c0, c1);
}

// ---------------- launch ----------------
extern "C" void kernel_launch(void* const* d_in, const int* in_sizes, int n_in,
                              void* d_out, int out_size)
{
    const float* x    = (const float*)d_in[0];
    const float* hm   = (const float*)d_in[1];
    const float* cm   = (const float*)d_in[2];
    const float* edge = (const float*)d_in[3];
    const float* Wiou = (const float*)d_in[4];
    const float* Wf   = (const float*)d_in[5];
    const float* Uiou = (const float*)d_in[6];
    const float* Uf   = (const float*)d_in[7];
    const float* biou = (const float*)d_in[8];
    const float* bf   = (const float*)d_in[9];
    float* out = (float*)d_out;

    k_init<<<(M_PAD + 255) / 256, 256>>>();
    k_perm<<<M_ROWS / 256, 256>>>(edge);
    k_reduce<<<(N_NODES * 128) / 256, 256>>>(hm, edge);
    k_gemm_x<<<dim3(2048 / 64, N_NODES / 128), 256>>>(x, Wiou, Wf);
    k_fgemm<<<dim3(512 / 64, M_PAD / 128), 256>>>(hm, Uf, bf, cm);
    k_gemm_iou<<<dim3(1536 / 64, N_NODES / 128), 256>>>(Uiou);
    k_final<<<(N_NODES * 256) / 256, 256>>>(biou, out);
}

// round 6
// speedup vs baseline: 1.4190x; 1.0020x over previous
#include <cuda_runtime.h>
#include <cstdint>
#include <cstddef>

#define N_NODES 8192
#define H_DIM   512
#define M_ROWS  (N_NODES * 8)        // 65536 mailbox rows
#define M_PAD   (M_ROWS + 256)       // 65792 = 514 * 128 (gap >= 128 -> no mixed tiles)
#define SENT    0xFFFFFFFFu

// ---------------- scratch (static device arrays; no runtime allocs) ----------------
__device__ float    g_ioux[(size_t)N_NODES * 1536];  // x @ W_iou                [N, 3H]
__device__ float    g_wfx [(size_t)N_NODES * 512];   // x @ W_f                  [N, H]
__device__ float    g_S   [(size_t)N_NODES * 1024];  // [s0 | s1]                [N, 2H]
__device__ float    g_mid [(size_t)N_NODES * 1536];  // S @ U_iou                [N, 3H]
__device__ float    g_fc  [(size_t)M_ROWS * 512];    // f * c_mail (scattered)   [N*K, H]
__device__ unsigned g_perm[M_PAD];
__device__ unsigned g_ctr[2];

// ---------------- helpers ----------------
__device__ __forceinline__ uint32_t f2tf(float x) {
    uint32_t r;
    asm("cvt.rna.tf32.f32 %0, %1;" : "=r"(r) : "f"(x));
    return r;
}

__device__ __forceinline__ void mma8(float (&c)[4], const uint32_t (&a)[4], const uint32_t (&b)[2]) {
    asm volatile(
        "mma.sync.aligned.m16n8k8.row.col.f32.tf32.tf32.f32 "
        "{%0,%1,%2,%3}, {%4,%5,%6,%7}, {%8,%9}, {%0,%1,%2,%3};"
        : "+f"(c[0]), "+f"(c[1]), "+f"(c[2]), "+f"(c[3])
        : "r"(a[0]), "r"(a[1]), "r"(a[2]), "r"(a[3]), "r"(b[0]), "r"(b[1]));
}

__device__ __forceinline__ float sigmoidf_(float z) {
    return __fdividef(1.0f, 1.0f + __expf(-z));
}

// ---------------- shared tiles (double-buffered, XOR-swizzled, zero padding) ----------
// A tile 128x32, phys col = col ^ ((row&7)<<2). B tile 32x64, phys col = col ^ ((row&3)<<3).
// Exactly 49152 bytes -> 2 CTAs/SM.
struct SmemT {
    uint32_t A[2][128][32];
    uint32_t B[2][32][64];
};

// ---------------- NB=1 tf32 GEMM core: 128x64xK, 256 thr, 2-stage smem pipeline -------
__device__ __forceinline__ void gemm_core(
    const float* a0, const float* a1, const float* a2, const float* a3,  // row base ptrs
    const float* __restrict__ B, int ldb, int Kdim,
    SmemT& sm, float (&acc)[2][4][4])
{
    const int tid  = threadIdx.x;
    const int lane = tid & 31;
    const int wm   = (tid >> 5) >> 1;   // 0..3
    const int wn   = (tid >> 5) & 1;    // 0..1
    const int g    = lane >> 2;         // 0..7
    const int t    = lane & 3;          // 0..3

    const int ar   = tid >> 3;          // A row 0..31 (+32*rr)
    const int ac4  = (tid & 7) << 2;    // A col 0..28
    const int bkr  = tid >> 4;          // B k 0..15 (+16*p)
    const int bc4  = (tid & 15) << 2;   // B col 0..60
    const int aswz = ac4 ^ ((ar & 7) << 2);
    const int bswz = bc4 ^ ((bkr & 3) << 3);

    const float* arow[4] = {a0, a1, a2, a3};
    float4 rA[4];
    float4 rB[2];

    auto ldg = [&](int kt) {
#pragma unroll
        for (int rr = 0; rr < 4; rr++)
            rA[rr] = *reinterpret_cast<const float4*>(arow[rr] + kt + ac4);
#pragma unroll
        for (int p = 0; p < 2; p++)
            rB[p] = *reinterpret_cast<const float4*>(B + (size_t)(kt + bkr + p * 16) * ldb + bc4);
    };
    auto sts = [&](int buf) {
#pragma unroll
        for (int rr = 0; rr < 4; rr++) {
            uint4 u;
            u.x = f2tf(rA[rr].x); u.y = f2tf(rA[rr].y);
            u.z = f2tf(rA[rr].z); u.w = f2tf(rA[rr].w);
            *reinterpret_cast<uint4*>(&sm.A[buf][ar + rr * 32][aswz]) = u;
        }
#pragma unroll
        for (int p = 0; p < 2; p++) {
            uint4 u;
            u.x = f2tf(rB[p].x); u.y = f2tf(rB[p].y);
            u.z = f2tf(rB[p].z); u.w = f2tf(rB[p].w);
            *reinterpret_cast<uint4*>(&sm.B[buf][bkr + p * 16][bswz]) = u;
        }
    };

    ldg(0);
    sts(0);
    __syncthreads();

    int buf = 0;
    for (int kt = 0; kt < Kdim; kt += 32, buf ^= 1) {
        const bool nxt = (kt + 32) < Kdim;
        if (nxt) ldg(kt + 32);          // LDGs in flight over compute

#pragma unroll
        for (int ks = 0; ks < 4; ks++) {
            const int kb = ks << 3;
            const int ca = (kb + t) ^ (g << 2);
            const int cb2 = (kb + t + 4) ^ (g << 2);
            uint32_t af[2][4];
#pragma unroll
            for (int mf = 0; mf < 2; mf++) {
                const int rb = wm * 32 + mf * 16;
                af[mf][0] = sm.A[buf][rb + g    ][ca];
                af[mf][1] = sm.A[buf][rb + 8 + g][ca];
                af[mf][2] = sm.A[buf][rb + g    ][cb2];
                af[mf][3] = sm.A[buf][rb + 8 + g][cb2];
            }
#pragma unroll
            for (int nf = 0; nf < 4; nf++) {
                const int cc = (wn * 32 + nf * 8 + g) ^ (t << 3);
                uint32_t bfr[2];
                bfr[0] = sm.B[buf][kb + t    ][cc];
                bfr[1] = sm.B[buf][kb + t + 4][cc];
#pragma unroll
                for (int mf = 0; mf < 2; mf++)
                    mma8(acc[mf][nf], af[mf], bfr);
            }
        }
        if (nxt) sts(buf ^ 1);          // buf^1 fully consumed before prior sync
        __syncthreads();
    }
}

// ---------------- K_init / K_perm: label-partition of mailbox rows ---------------------
__global__ void k_init() {
    const int idx = blockIdx.x * blockDim.x + threadIdx.x;
    if (idx < M_PAD) g_perm[idx] = SENT;
    if (idx < 2) g_ctr[idx] = 0u;
}

__global__ void k_perm(const float* __restrict__ edge) {
    const int r = blockIdx.x * blockDim.x + threadIdx.x;
    if (r >= M_ROWS) return;
    const float e = edge[r];
    if (e < 0.5f) {
        const unsigned pos = atomicAdd(&g_ctr[0], 1u);
        g_perm[pos] = (unsigned)r;
    } else {
        const unsigned pos = atomicAdd(&g_ctr[1], 1u);
        g_perm[M_PAD - 1 - pos] = (unsigned)r;
    }
}

// ---------------- K_reduce: mailbox label-routed sum -> g_S = [s0 | s1] ----------------
__global__ void k_reduce(const float* __restrict__ hm, const float* __restrict__ edge) {
    const int idx = blockIdx.x * blockDim.x + threadIdx.x;   // 0 .. N*128-1
    const int n = idx >> 7;
    const int j = (idx & 127) << 2;
    const float* p = hm + (size_t)n * 4096 + j;
    float4 s0 = make_float4(0.f, 0.f, 0.f, 0.f);
    float4 s1 = make_float4(0.f, 0.f, 0.f, 0.f);
#pragma unroll
    for (int k = 0; k < 8; k++) {
        const float e = __ldg(edge + n * 8 + k);
        const float4 v = *reinterpret_cast<const float4*>(p + k * 512);
        s1.x += e * v.x; s1.y += e * v.y; s1.z += e * v.z; s1.w += e * v.w;
        s0.x += v.x - e * v.x; s0.y += v.y - e * v.y;
        s0.z += v.z - e * v.z; s0.w += v.w - e * v.w;
    }
    *reinterpret_cast<float4*>(&g_S[(size_t)n * 1024 + j])       = s0;
    *reinterpret_cast<float4*>(&g_S[(size_t)n * 1024 + 512 + j]) = s1;
}

// ---------------- K_A: x @ [W_iou | W_f] -> g_ioux / g_wfx -----------------------------
__global__ __launch_bounds__(256, 2) void k_gemm_x(
    const float* __restrict__ x, const float* __restrict__ Wiou, const float* __restrict__ Wf)
{
    __shared__ SmemT sm;
    const int m0 = blockIdx.y * 128, n0 = blockIdx.x * 64;

    const float* B; int ldb; float* C; int ldc; int ccol;
    if (n0 < 1536) { B = Wiou + n0;          ldb = 1536; C = g_ioux; ldc = 1536; ccol = n0; }
    else           { B = Wf + (n0 - 1536);   ldb = 512;  C = g_wfx;  ldc = 512;  ccol = n0 - 1536; }

    const int tid = threadIdx.x, ar = tid >> 3;
    const float* a0 = x + (size_t)(m0 + ar)      * 512;
    const float* a1 = x + (size_t)(m0 + ar + 32) * 512;
    const float* a2 = x + (size_t)(m0 + ar + 64) * 512;
    const float* a3 = x + (size_t)(m0 + ar + 96) * 512;

    float acc[2][4][4];
    float* af = &acc[0][0][0];
#pragma unroll
    for (int i = 0; i < 32; i++) af[i] = 0.f;

    gemm_core(a0, a1, a2, a3, B, ldb, 512, sm, acc);

    const int lane = tid & 31;
    const int wm = (tid >> 5) >> 1, wn = (tid >> 5) & 1;
    const int g = lane >> 2, t = lane & 3;
#pragma unroll
    for (int mf = 0; mf < 2; mf++)
#pragma unroll
        for (int rh = 0; rh < 2; rh++) {
            const int row = m0 + wm * 32 + mf * 16 + rh * 8 + g;
#pragma unroll
            for (int nf = 0; nf < 4; nf++) {
                const int col = ccol + wn * 32 + nf * 8 + t * 2;
                *reinterpret_cast<float2*>(C + (size_t)row * ldc + col) =
                    make_float2(acc[mf][nf][rh * 2], acc[mf][nf][rh * 2 + 1]);
            }
        }
}

// ---------------- K_F: gathered f-gate GEMM (NB=1, label-uniform tiles) ----------------
__global__ __launch_bounds__(256, 2) void k_fgemm(
    const float* __restrict__ hm, const float* __restrict__ Uf,
    const float* __restrict__ bf_, const float* __restrict__ cmail)
{
    __shared__ SmemT sm;
    const int m0 = blockIdx.y * 128, n0 = blockIdx.x * 64;

    const unsigned c0 = g_ctr[0];                       // finalized by k_perm
    const int label = (m0 < (int)c0) ? 0 : 1;           // tiles never mix labels
    const float* B = Uf + (size_t)label * 512 * 512 + n0;

    const int tid = threadIdx.x, ar = tid >> 3;
    const float* ap[4];
#pragma unroll
    for (int rr = 0; rr < 4; rr++) {
        const unsigned p = g_perm[m0 + ar + rr * 32];
        ap[rr] = hm + (size_t)(p == SENT ? 0u : p) * 512;
    }

    float acc[2][4][4];
    float* af = &acc[0][0][0];
#pragma unroll
    for (int i = 0; i < 32; i++) af[i] = 0.f;

    gemm_core(ap[0], ap[1], ap[2], ap[3], B, 512, 512, sm, acc);

    const int lane = tid & 31;
    const int wm = (tid >> 5) >> 1, wn = (tid >> 5) & 1;
    const int g = lane >> 2, t = lane & 3;
#pragma unroll
    for (int mf = 0; mf < 2; mf++)
#pragma unroll
        for (int rh = 0; rh < 2; rh++) {
            const unsigned p = g_perm[m0 + wm * 32 + mf * 16 + rh * 8 + g];
            if (p == SENT) continue;
            const int node = (int)(p >> 3);
#pragma unroll
            for (int nf = 0; nf < 4; nf++) {
                const int col = n0 + wn * 32 + nf * 8 + t * 2;
                float v[2];
#pragma unroll
                for (int q = 0; q < 2; q++) {
                    const float z = g_wfx[(size_t)node * 512 + col + q]
                                  + acc[mf][nf][rh * 2 + q]
                                  + __ldg(bf_ + col + q);
                    v[q] = sigmoidf_(z) * __ldg(cmail + (size_t)p * 512 + col + q);
                }
                *reinterpret_cast<float2*>(&g_fc[(size_t)p * 512 + col]) =
                    make_float2(v[0], v[1]);
            }
        }
}

// ---------------- K_G: S @ U_iou -> g_mid ----------------------------------------------
__global__ __launch_bounds__(256, 2) void k_gemm_iou(const float* __restrict__ Uiou)
{
    __shared__ SmemT sm;
    const int m0 = blockIdx.y * 128, n0 = blockIdx.x * 64;
    const float* B = Uiou + n0;

    const int tid = threadIdx.x, ar = tid >> 3;
    const float* a0 = g_S + (size_t)(m0 + ar)      * 1024;
    const float* a1 = g_S + (size_t)(m0 + ar + 32) * 1024;
    const float* a2 = g_S + (size_t)(m0 + ar + 64) * 1024;
    const float* a3 = g_S + (size_t)(m0 + ar + 96) * 1024;

    float acc[2][4][4];
    float* af = &acc[0][0][0];
#pragma unroll
    for (int i = 0; i < 32; i++) af[i] = 0.f;

    gemm_core(a0, a1, a2, a3, B, 1536, 1024, sm, acc);

    const int lane = tid & 31;
    const int wm = (tid >> 5) >> 1, wn = (tid >> 5) & 1;
    const int g = lane >> 2, t = lane & 3;
#pragma unroll
    for (int mf = 0; mf < 2; mf++)
#pragma unroll
        for (int rh = 0; rh < 2; rh++) {
            const int row = m0 + wm * 32 + mf * 16 + rh * 8 + g;
#pragma unroll
            for (int nf = 0; nf < 4; nf++) {
                const int col = n0 + wn * 32 + nf * 8 + t * 2;
                *reinterpret_cast<float2*>(&g_mid[(size_t)row * 1536 + col]) =
                    make_float2(acc[mf][nf][rh * 2], acc[mf][nf][rh * 2 + 1]);
            }
        }
}

// ---------------- K_E: elementwise finalize (iou + c_agg sum) -> out = [h | c] ---------
__global__ void k_final(const float* __restrict__ biou, float* __restrict__ out)
{
    const int idx = blockIdx.x * blockDim.x + threadIdx.x;   // 0 .. N*256-1
    const int n = idx >> 8;
    const int col = (idx & 255) << 1;
    const size_t b3 = (size_t)n * 1536 + col;

    const float2 mi = *reinterpret_cast<const float2*>(&g_mid[b3]);
    const float2 mo = *reinterpret_cast<const float2*>(&g_mid[b3 + 512]);
    const float2 mu = *reinterpret_cast<const float2*>(&g_mid[b3 + 1024]);
    const float2 xi = *reinterpret_cast<const float2*>(&g_ioux[b3]);
    const float2 xo = *reinterpret_cast<const float2*>(&g_ioux[b3 + 512]);
    const float2 xu = *reinterpret_cast<const float2*>(&g_ioux[b3 + 1024]);
    const float2 bi = *reinterpret_cast<const float2*>(&biou[col]);
    const float2 bo = *reinterpret_cast<const float2*>(&biou[col + 512]);
    const float2 bu = *reinterpret_cast<const float2*>(&biou[col + 1024]);

    float cax = 0.f, cay = 0.f;
#pragma unroll
    for (int k = 0; k < 8; k++) {
        const float2 v = *reinterpret_cast<const float2*>(&g_fc[((size_t)n * 8 + k) * 512 + col]);
        cax += v.x; cay += v.y;
    }

    const float iv0 = sigmoidf_(mi.x + xi.x + bi.x);
    const float iv1 = sigmoidf_(mi.y + xi.y + bi.y);
    const float ov0 = sigmoidf_(mo.x + xo.x + bo.x);
    const float ov1 = sigmoidf_(mo.y + xo.y + bo.y);
    const float uv0 = tanhf(mu.x + xu.x + bu.x);
    const float uv1 = tanhf(mu.y + xu.y + bu.y);

    const float c0 = iv0 * uv0 + cax;
    const float c1 = iv1 * uv1 + cay;
    const float h0 = ov0 * tanhf(c0);
    const float h1 = ov1 * tanhf(c1);

    *reinterpret_cast<float2*>(&out[(size_t)n * 512 + col]) = make_float2(h0, h1);
    *reinterpret_cast<float2*>(&out[(size_t)(N_NODES + n) * 512 + col]) = make_float2(c0, c1);
}

// ---------------- launch ----------------
extern "C" void kernel_launch(void* const* d_in, const int* in_sizes, int n_in,
                              void* d_out, int out_size)
{
    const float* x    = (const float*)d_in[0];
    const float* hm   = (const float*)d_in[1];
    const float* cm   = (const float*)d_in[2];
    const float* edge = (const float*)d_in[3];
    const float* Wiou = (const float*)d_in[4];
    const float* Wf   = (const float*)d_in[5];
    const float* Uiou = (const float*)d_in[6];
    const float* Uf   = (const float*)d_in[7];
    const float* biou = (const float*)d_in[8];
    const float* bf   = (const float*)d_in[9];
    float* out = (float*)d_out;

    k_init<<<(M_PAD + 255) / 256, 256>>>();
    k_perm<<<M_ROWS / 256, 256>>>(edge);
    k_reduce<<<(N_NODES * 128) / 256, 256>>>(hm, edge);
    k_gemm_x<<<dim3(2048 / 64, N_NODES / 128), 256>>>(x, Wiou, Wf);
    k_fgemm<<<dim3(512 / 64, M_PAD / 128), 256>>>(hm, Uf, bf, cm);
    k_gemm_iou<<<dim3(1536 / 64, N_NODES / 128), 256>>>(Uiou);
    k_final<<<(N_NODES * 256) / 256, 256>>>(biou, out);
}